// round 3
// baseline (speedup 1.0000x reference)
#include <cuda_runtime.h>
#include <math.h>

// Problem constants
#define NB      16
#define HW      262144           // 512*512
#define KRANK   104856u          // int(512*512*0.4 - 1)
#define NBINS1  16384            // high-16 bits of gray < 1.0 are < 16384 (clamped)
#define SEGS    256              // compaction segments per batch (= blocks per batch)
#define SEGCAP  128              // capacity per segment
#define TOTAL_ELEMS (16.0*3.0*512.0*512.0)

// Device scratch
__device__ float        g_gray[NB * HW];
__device__ unsigned int g_hist1[NB * NBINS1];            // 1 MB
__device__ unsigned int g_buf[NB * SEGS * SEGCAP];       // 2 MB
__device__ unsigned int g_segcnt[NB * SEGS];
__device__ unsigned int g_prefix[NB];
__device__ unsigned int g_rank[NB];
__device__ float        g_thr[NB];
__device__ float        g_partial[4096];

// ---------------------------------------------------------------------------
// K0: zero hist1 (1 MB).  256 blocks x 256 thr, uint4 stores.
// ---------------------------------------------------------------------------
__global__ void zero_scratch() {
    int i = blockIdx.x * blockDim.x + threadIdx.x;   // 0..65535 uint4
    ((uint4*)g_hist1)[i] = make_uint4(0u, 0u, 0u, 0u);
}

// ---------------------------------------------------------------------------
// K1: gray = (c0+c1+c2)/3, store gray, high-16 histogram (no-return REDG).
// 4096 blocks x 256 thr; 1 float4 per channel per thread.
// ---------------------------------------------------------------------------
__global__ void pass1_gray_hist(const float* __restrict__ yp) {
    int idx = blockIdx.x * blockDim.x + threadIdx.x;   // 0 .. 1048575
    int b = idx >> 16;                                  // 65536 float4 per batch
    int p = idx & 65535;

    const float4* base = (const float4*)yp + (size_t)b * 3 * (HW/4);
    float4 a = base[0*(HW/4) + p];
    float4 x = base[1*(HW/4) + p];
    float4 y = base[2*(HW/4) + p];

    float4 g;
    g.x = (a.x + x.x + y.x) / 3.0f;
    g.y = (a.y + x.y + y.y) / 3.0f;
    g.z = (a.z + x.z + y.z) / 3.0f;
    g.w = (a.w + x.w + y.w) / 3.0f;

    ((float4*)g_gray)[(size_t)b * (HW/4) + p] = g;

    unsigned int* h = g_hist1 + (size_t)b * NBINS1;
    unsigned int i0 = __float_as_uint(g.x) >> 16; if (i0 > NBINS1-1) i0 = NBINS1-1;
    unsigned int i1 = __float_as_uint(g.y) >> 16; if (i1 > NBINS1-1) i1 = NBINS1-1;
    unsigned int i2 = __float_as_uint(g.z) >> 16; if (i2 > NBINS1-1) i2 = NBINS1-1;
    unsigned int i3 = __float_as_uint(g.w) >> 16; if (i3 > NBINS1-1) i3 = NBINS1-1;
    atomicAdd(&h[i0], 1u);
    atomicAdd(&h[i1], 1u);
    atomicAdd(&h[i2], 1u);
    atomicAdd(&h[i3], 1u);
}

// ---------------------------------------------------------------------------
// K2: select high-16 bin containing rank KRANK.  16 blocks x 256 thr.
// 64 chunks of 256 bins; warp w handles chunks w, w+8, ... (coalesced uint4).
// ---------------------------------------------------------------------------
__global__ void select1() {
    int b = blockIdx.x;
    const uint4* h4 = (const uint4*)(g_hist1 + (size_t)b * NBINS1);  // 4096 uint4
    __shared__ unsigned int partial[64];
    __shared__ unsigned int fine[256];
    __shared__ int s_chunk;
    __shared__ unsigned int s_rem;

    int warp = threadIdx.x >> 5;
    int lane = threadIdx.x & 31;

    #pragma unroll
    for (int it = 0; it < 8; it++) {
        int c = warp + 8 * it;                       // chunk 0..63 (256 bins each)
        uint4 v1 = h4[c * 64 + lane];
        uint4 v2 = h4[c * 64 + 32 + lane];
        unsigned int s = v1.x+v1.y+v1.z+v1.w + v2.x+v2.y+v2.z+v2.w;
        #pragma unroll
        for (int o = 16; o > 0; o >>= 1) s += __shfl_down_sync(0xFFFFFFFFu, s, o);
        if (lane == 0) partial[c] = s;
    }
    __syncthreads();

    if (threadIdx.x == 0) {
        unsigned int k = KRANK, cum = 0;
        int cb = 63;
        for (int j = 0; j < 64; j++) {
            if (k < cum + partial[j]) { cb = j; break; }
            cum += partial[j];
        }
        s_chunk = cb; s_rem = k - cum;
    }
    __syncthreads();

    int cb = s_chunk;
    fine[threadIdx.x] = g_hist1[(size_t)b * NBINS1 + cb * 256 + threadIdx.x];
    __syncthreads();

    if (threadIdx.x == 0) {
        unsigned int k = s_rem, cum = 0;
        int fb = 255;
        for (int i = 0; i < 256; i++) {
            if (k < cum + fine[i]) { fb = i; break; }
            cum += fine[i];
        }
        g_prefix[b] = (unsigned int)(cb * 256 + fb);
        g_rank[b]   = k - cum;
    }
}

// ---------------------------------------------------------------------------
// K3: compact matching gray values into per-block segments (smem counter only).
// 4096 blocks x 256 thr; blockIdx.x = b*256 + seg.
// ---------------------------------------------------------------------------
__global__ void pass2_compact() {
    int idx = blockIdx.x * blockDim.x + threadIdx.x;
    int b = idx >> 16;
    int p = idx & 65535;
    unsigned int prefix = g_prefix[b];

    __shared__ unsigned int s_cnt;
    if (threadIdx.x == 0) s_cnt = 0u;
    __syncthreads();

    float4 g = ((const float4*)g_gray)[(size_t)b * (HW/4) + p];
    unsigned int v[4];
    v[0] = __float_as_uint(g.x); v[1] = __float_as_uint(g.y);
    v[2] = __float_as_uint(g.z); v[3] = __float_as_uint(g.w);

    unsigned int* seg = g_buf + (size_t)blockIdx.x * SEGCAP;
    #pragma unroll
    for (int i = 0; i < 4; i++) {
        if ((v[i] >> 16) == prefix) {
            unsigned int pos = atomicAdd(&s_cnt, 1u);
            if (pos < SEGCAP) seg[pos] = v[i];
        }
    }
    __syncthreads();
    if (threadIdx.x == 0)
        g_segcnt[blockIdx.x] = (s_cnt < SEGCAP) ? s_cnt : SEGCAP;
}

// ---------------------------------------------------------------------------
// K4: exact low-16 selection over compacted segments.  16 blocks x 256 thr.
// ---------------------------------------------------------------------------
__global__ void select2() {
    int b = blockIdx.x;
    const unsigned int* buf = g_buf + (size_t)b * SEGS * SEGCAP;

    __shared__ unsigned int cnts[SEGS];
    __shared__ unsigned int hist[256];
    __shared__ int s_b1;
    __shared__ unsigned int s_rem;

    int t = threadIdx.x;
    cnts[t] = g_segcnt[b * SEGS + t];
    hist[t] = 0u;
    __syncthreads();

    for (int i = t; i < SEGS * SEGCAP; i += 256) {
        int seg = i >> 7;                  // SEGCAP = 128
        int pos = i & (SEGCAP - 1);
        if ((unsigned int)pos < cnts[seg])
            atomicAdd(&hist[(buf[i] >> 8) & 0xFFu], 1u);
    }
    __syncthreads();

    if (t == 0) {
        unsigned int k = g_rank[b], cum = 0;
        int b1 = 255;
        for (int i = 0; i < 256; i++) {
            if (k < cum + hist[i]) { b1 = i; break; }
            cum += hist[i];
        }
        s_b1 = b1; s_rem = k - cum;
    }
    __syncthreads();
    hist[t] = 0u;
    __syncthreads();

    int b1 = s_b1;
    for (int i = t; i < SEGS * SEGCAP; i += 256) {
        int seg = i >> 7;
        int pos = i & (SEGCAP - 1);
        if ((unsigned int)pos < cnts[seg]) {
            unsigned int w = buf[i];
            if (((w >> 8) & 0xFFu) == (unsigned int)b1)
                atomicAdd(&hist[w & 0xFFu], 1u);
        }
    }
    __syncthreads();

    if (t == 0) {
        unsigned int k = s_rem, cum = 0;
        int b0 = 255;
        for (int i = 0; i < 256; i++) {
            if (k < cum + hist[i]) { b0 = i; break; }
            cum += hist[i];
        }
        g_thr[b] = __uint_as_float((g_prefix[b] << 16) |
                                   ((unsigned int)b1 << 8) | (unsigned int)b0);
    }
}

// ---------------------------------------------------------------------------
// K5: weighted L1 + block reduce -> plain store of per-block partial.
// 4096 blocks x 256 thr; 1 float4 per array per thread.
// ---------------------------------------------------------------------------
__global__ void pass3_loss(const float* __restrict__ yt,
                           const float* __restrict__ yp) {
    int idx = blockIdx.x * blockDim.x + threadIdx.x;
    int b = idx >> 16;
    int p = idx & 65535;
    float thr = g_thr[b];

    size_t base4 = (size_t)b * 3 * (HW/4);
    float4 a = ((const float4*)yp)[base4 + 0*(HW/4) + p];
    float4 x = ((const float4*)yp)[base4 + 1*(HW/4) + p];
    float4 y = ((const float4*)yp)[base4 + 2*(HW/4) + p];
    float4 u = ((const float4*)yt)[base4 + 0*(HW/4) + p];
    float4 v = ((const float4*)yt)[base4 + 1*(HW/4) + p];
    float4 w = ((const float4*)yt)[base4 + 2*(HW/4) + p];

    float s = 0.0f;
    float gray, wt;
    gray = (a.x + x.x + y.x) / 3.0f;
    wt = (gray <= thr) ? 0.8f : 0.2f;
    s += wt * (fabsf(a.x-u.x) + fabsf(x.x-v.x) + fabsf(y.x-w.x));
    gray = (a.y + x.y + y.y) / 3.0f;
    wt = (gray <= thr) ? 0.8f : 0.2f;
    s += wt * (fabsf(a.y-u.y) + fabsf(x.y-v.y) + fabsf(y.y-w.y));
    gray = (a.z + x.z + y.z) / 3.0f;
    wt = (gray <= thr) ? 0.8f : 0.2f;
    s += wt * (fabsf(a.z-u.z) + fabsf(x.z-v.z) + fabsf(y.z-w.z));
    gray = (a.w + x.w + y.w) / 3.0f;
    wt = (gray <= thr) ? 0.8f : 0.2f;
    s += wt * (fabsf(a.w-u.w) + fabsf(x.w-v.w) + fabsf(y.w-w.w));

    #pragma unroll
    for (int o = 16; o > 0; o >>= 1)
        s += __shfl_down_sync(0xFFFFFFFFu, s, o);

    __shared__ float ws[8];
    int lane = threadIdx.x & 31;
    int warp = threadIdx.x >> 5;
    if (lane == 0) ws[warp] = s;
    __syncthreads();
    if (warp == 0) {
        float vv = (lane < 8) ? ws[lane] : 0.0f;
        #pragma unroll
        for (int o = 4; o > 0; o >>= 1)
            vv += __shfl_down_sync(0xFFFFFFFFu, vv, o);
        if (lane == 0) g_partial[blockIdx.x] = vv;
    }
}

// ---------------------------------------------------------------------------
// K6: final reduction of 4096 partials (double accumulation).  1 block x 1024.
// ---------------------------------------------------------------------------
__global__ void finalize(float* __restrict__ out) {
    int t = threadIdx.x;
    double s = 0.0;
    #pragma unroll
    for (int i = 0; i < 4; i++)
        s += (double)g_partial[t + i * 1024];

    #pragma unroll
    for (int o = 16; o > 0; o >>= 1)
        s += __shfl_down_sync(0xFFFFFFFFu, s, o);

    __shared__ double ws[32];
    int lane = t & 31;
    int warp = t >> 5;
    if (lane == 0) ws[warp] = s;
    __syncthreads();
    if (warp == 0) {
        double v = (lane < 32) ? ws[lane] : 0.0;
        #pragma unroll
        for (int o = 16; o > 0; o >>= 1)
            v += __shfl_down_sync(0xFFFFFFFFu, v, o);
        if (lane == 0) out[0] = (float)(v / TOTAL_ELEMS);
    }
}

// ---------------------------------------------------------------------------
extern "C" void kernel_launch(void* const* d_in, const int* in_sizes, int n_in,
                              void* d_out, int out_size) {
    const float* y_true = (const float*)d_in[0];
    const float* y_pred = (const float*)d_in[1];
    float* out = (float*)d_out;

    zero_scratch<<<256, 256>>>();
    pass1_gray_hist<<<4096, 256>>>(y_pred);
    select1<<<NB, 256>>>();
    pass2_compact<<<4096, 256>>>();
    select2<<<NB, 256>>>();
    pass3_loss<<<4096, 256>>>(y_true, y_pred);
    finalize<<<1, 1024>>>(out);
}

// round 4
// speedup vs baseline: 3.7030x; 3.7030x over previous
#include <cuda_runtime.h>
#include <math.h>

// Problem constants
#define NB      16
#define HW      262144           // 512*512
#define KRANK   104856u          // int(512*512*0.4 - 1)
#define NBINS   16384            // value-space bins: bin = min(16383, int(gray*16384))
#define CAP     4096             // per-batch candidate capacity (expected ~24)
#define TOTAL_ELEMS (16.0*3.0*512.0*512.0)

// Device scratch
__device__ float        g_gray[NB * HW];
__device__ unsigned int g_hist[NB * NBINS];       // 1 MB
__device__ unsigned int g_cnt[NB];
__device__ float        g_buf[NB * CAP];
__device__ unsigned int g_bin[NB];
__device__ unsigned int g_rank[NB];
__device__ float        g_thr[NB];
__device__ float        g_partial[1024];

__device__ __forceinline__ unsigned int gray_bin(float g) {
    int v = (int)(g * 16384.0f);
    if (v > NBINS - 1) v = NBINS - 1;
    if (v < 0) v = 0;
    return (unsigned int)v;
}

// ---------------------------------------------------------------------------
// K0: zero hist (1 MB) + counters.  256 blocks x 256 thr.
// ---------------------------------------------------------------------------
__global__ void zero_scratch() {
    int i = blockIdx.x * blockDim.x + threadIdx.x;   // 0..65535 uint4
    ((uint4*)g_hist)[i] = make_uint4(0u, 0u, 0u, 0u);
    if (i < NB) g_cnt[i] = 0u;
}

// ---------------------------------------------------------------------------
// K1: gray = (c0+c1+c2)/3, store gray, value-space histogram (REDG, spread).
// 1024 blocks (64/batch) x 256 thr; 16 px/thread.
// ---------------------------------------------------------------------------
__global__ void pass1_gray_hist(const float* __restrict__ yp) {
    int b = blockIdx.x >> 6;
    int r = blockIdx.x & 63;
    int t = threadIdx.x;

    const float4* c0 = (const float4*)yp + (size_t)b * 3 * (HW/4) + 0 * (HW/4) + r * 1024;
    const float4* c1 = (const float4*)yp + (size_t)b * 3 * (HW/4) + 1 * (HW/4) + r * 1024;
    const float4* c2 = (const float4*)yp + (size_t)b * 3 * (HW/4) + 2 * (HW/4) + r * 1024;
    float4* gr = (float4*)g_gray + (size_t)b * (HW/4) + r * 1024;
    unsigned int* h = g_hist + (size_t)b * NBINS;

    float4 a0 = c0[t], a1 = c0[t+256], a2 = c0[t+512], a3 = c0[t+768];
    float4 x0 = c1[t], x1 = c1[t+256], x2 = c1[t+512], x3 = c1[t+768];
    float4 y0 = c2[t], y1 = c2[t+256], y2 = c2[t+512], y3 = c2[t+768];

    float4 g0, g1, g2, g3;
    g0.x=(a0.x+x0.x+y0.x)/3.0f; g0.y=(a0.y+x0.y+y0.y)/3.0f; g0.z=(a0.z+x0.z+y0.z)/3.0f; g0.w=(a0.w+x0.w+y0.w)/3.0f;
    g1.x=(a1.x+x1.x+y1.x)/3.0f; g1.y=(a1.y+x1.y+y1.y)/3.0f; g1.z=(a1.z+x1.z+y1.z)/3.0f; g1.w=(a1.w+x1.w+y1.w)/3.0f;
    g2.x=(a2.x+x2.x+y2.x)/3.0f; g2.y=(a2.y+x2.y+y2.y)/3.0f; g2.z=(a2.z+x2.z+y2.z)/3.0f; g2.w=(a2.w+x2.w+y2.w)/3.0f;
    g3.x=(a3.x+x3.x+y3.x)/3.0f; g3.y=(a3.y+x3.y+y3.y)/3.0f; g3.z=(a3.z+x3.z+y3.z)/3.0f; g3.w=(a3.w+x3.w+y3.w)/3.0f;

    gr[t] = g0; gr[t+256] = g1; gr[t+512] = g2; gr[t+768] = g3;

    atomicAdd(&h[gray_bin(g0.x)],1u); atomicAdd(&h[gray_bin(g0.y)],1u);
    atomicAdd(&h[gray_bin(g0.z)],1u); atomicAdd(&h[gray_bin(g0.w)],1u);
    atomicAdd(&h[gray_bin(g1.x)],1u); atomicAdd(&h[gray_bin(g1.y)],1u);
    atomicAdd(&h[gray_bin(g1.z)],1u); atomicAdd(&h[gray_bin(g1.w)],1u);
    atomicAdd(&h[gray_bin(g2.x)],1u); atomicAdd(&h[gray_bin(g2.y)],1u);
    atomicAdd(&h[gray_bin(g2.z)],1u); atomicAdd(&h[gray_bin(g2.w)],1u);
    atomicAdd(&h[gray_bin(g3.x)],1u); atomicAdd(&h[gray_bin(g3.y)],1u);
    atomicAdd(&h[gray_bin(g3.z)],1u); atomicAdd(&h[gray_bin(g3.w)],1u);
}

// ---------------------------------------------------------------------------
// K2: find value-bin containing rank KRANK.  16 blocks x 256 thr.
// 64 chunks of 256 bins; warp w sums chunks w, w+8, ... (coalesced uint4).
// ---------------------------------------------------------------------------
__global__ void select1() {
    int b = blockIdx.x;
    const uint4* h4 = (const uint4*)(g_hist + (size_t)b * NBINS);  // 4096 uint4
    __shared__ unsigned int partial[64];
    __shared__ unsigned int fine[256];
    __shared__ int s_chunk;
    __shared__ unsigned int s_rem;

    int warp = threadIdx.x >> 5;
    int lane = threadIdx.x & 31;

    #pragma unroll
    for (int it = 0; it < 8; it++) {
        int c = warp + 8 * it;
        uint4 v1 = h4[c * 64 + lane];
        uint4 v2 = h4[c * 64 + 32 + lane];
        unsigned int s = v1.x+v1.y+v1.z+v1.w + v2.x+v2.y+v2.z+v2.w;
        #pragma unroll
        for (int o = 16; o > 0; o >>= 1) s += __shfl_down_sync(0xFFFFFFFFu, s, o);
        if (lane == 0) partial[c] = s;
    }
    __syncthreads();

    if (threadIdx.x == 0) {
        unsigned int k = KRANK, cum = 0;
        int cb = 63;
        for (int j = 0; j < 64; j++) {
            if (k < cum + partial[j]) { cb = j; break; }
            cum += partial[j];
        }
        s_chunk = cb; s_rem = k - cum;
    }
    __syncthreads();

    int cb = s_chunk;
    fine[threadIdx.x] = g_hist[(size_t)b * NBINS + cb * 256 + threadIdx.x];
    __syncthreads();

    if (threadIdx.x == 0) {
        unsigned int k = s_rem, cum = 0;
        int fb = 255;
        for (int i = 0; i < 256; i++) {
            if (k < cum + fine[i]) { fb = i; break; }
            cum += fine[i];
        }
        g_bin[b]  = (unsigned int)(cb * 256 + fb);
        g_rank[b] = k - cum;        // rank within selected bin
    }
}

// ---------------------------------------------------------------------------
// K3: compact gray values in the selected bin (~24/batch).
// 1024 blocks x 256 thr; 16 px/thread.
// ---------------------------------------------------------------------------
__global__ void pass2_compact() {
    int b = blockIdx.x >> 6;
    int r = blockIdx.x & 63;
    int t = threadIdx.x;
    unsigned int bin = g_bin[b];

    const float4* gr = (const float4*)g_gray + (size_t)b * (HW/4) + r * 1024;
    float4 g0 = gr[t], g1 = gr[t+256], g2 = gr[t+512], g3 = gr[t+768];

    float v[16] = {g0.x,g0.y,g0.z,g0.w, g1.x,g1.y,g1.z,g1.w,
                   g2.x,g2.y,g2.z,g2.w, g3.x,g3.y,g3.z,g3.w};

    #pragma unroll
    for (int i = 0; i < 16; i++) {
        if (gray_bin(v[i]) == bin) {
            unsigned int p = atomicAdd(&g_cnt[b], 1u);
            if (p < CAP) g_buf[(size_t)b * CAP + p] = v[i];
        }
    }
}

// ---------------------------------------------------------------------------
// K4: exact rank selection among candidates.  16 blocks x 256 thr.
// ---------------------------------------------------------------------------
__global__ void select2() {
    int b = blockIdx.x;
    unsigned int n = g_cnt[b];
    if (n > CAP) n = CAP;
    unsigned int k = g_rank[b];

    __shared__ float vals[CAP];
    int t = threadIdx.x;
    for (unsigned int i = t; i < n; i += 256)
        vals[i] = g_buf[(size_t)b * CAP + i];
    __syncthreads();

    for (unsigned int i = t; i < n; i += 256) {
        float v = vals[i];
        unsigned int cl = 0, ce = 0;
        for (unsigned int j = 0; j < n; j++) {
            float w = vals[j];
            cl += (w < v);
            ce += (w == v);
        }
        if (cl <= k && k < cl + ce)
            g_thr[b] = v;                 // unique value; benign multi-write
    }
}

// ---------------------------------------------------------------------------
// K5: weighted L1 + block reduce -> per-block partial.
// 1024 blocks x 256 thr; 16 px/thread.
// ---------------------------------------------------------------------------
__global__ void pass3_loss(const float* __restrict__ yt,
                           const float* __restrict__ yp) {
    int b = blockIdx.x >> 6;
    int r = blockIdx.x & 63;
    int t = threadIdx.x;
    float thr = g_thr[b];

    size_t base4 = (size_t)b * 3 * (HW/4);
    const float4* p0 = (const float4*)yp + base4 + 0*(HW/4) + r*1024;
    const float4* p1 = (const float4*)yp + base4 + 1*(HW/4) + r*1024;
    const float4* p2 = (const float4*)yp + base4 + 2*(HW/4) + r*1024;
    const float4* q0 = (const float4*)yt + base4 + 0*(HW/4) + r*1024;
    const float4* q1 = (const float4*)yt + base4 + 1*(HW/4) + r*1024;
    const float4* q2 = (const float4*)yt + base4 + 2*(HW/4) + r*1024;

    float s = 0.0f;
    #pragma unroll
    for (int i = 0; i < 4; i++) {
        int o = t + i * 256;
        float4 a = p0[o], x = p1[o], y = p2[o];
        float4 u = q0[o], v = q1[o], w = q2[o];

        float gray, wt;
        gray = (a.x + x.x + y.x) / 3.0f;
        wt = (gray <= thr) ? 0.8f : 0.2f;
        s += wt * (fabsf(a.x-u.x) + fabsf(x.x-v.x) + fabsf(y.x-w.x));
        gray = (a.y + x.y + y.y) / 3.0f;
        wt = (gray <= thr) ? 0.8f : 0.2f;
        s += wt * (fabsf(a.y-u.y) + fabsf(x.y-v.y) + fabsf(y.y-w.y));
        gray = (a.z + x.z + y.z) / 3.0f;
        wt = (gray <= thr) ? 0.8f : 0.2f;
        s += wt * (fabsf(a.z-u.z) + fabsf(x.z-v.z) + fabsf(y.z-w.z));
        gray = (a.w + x.w + y.w) / 3.0f;
        wt = (gray <= thr) ? 0.8f : 0.2f;
        s += wt * (fabsf(a.w-u.w) + fabsf(x.w-v.w) + fabsf(y.w-w.w));
    }

    #pragma unroll
    for (int o = 16; o > 0; o >>= 1)
        s += __shfl_down_sync(0xFFFFFFFFu, s, o);

    __shared__ float ws[8];
    int lane = threadIdx.x & 31;
    int warp = threadIdx.x >> 5;
    if (lane == 0) ws[warp] = s;
    __syncthreads();
    if (warp == 0) {
        float vv = (lane < 8) ? ws[lane] : 0.0f;
        #pragma unroll
        for (int o = 4; o > 0; o >>= 1)
            vv += __shfl_down_sync(0xFFFFFFFFu, vv, o);
        if (lane == 0) g_partial[blockIdx.x] = vv;
    }
}

// ---------------------------------------------------------------------------
// K6: final reduction of 1024 partials (double).  1 block x 1024.
// ---------------------------------------------------------------------------
__global__ void finalize(float* __restrict__ out) {
    int t = threadIdx.x;
    double s = (double)g_partial[t];

    #pragma unroll
    for (int o = 16; o > 0; o >>= 1)
        s += __shfl_down_sync(0xFFFFFFFFu, s, o);

    __shared__ double ws[32];
    int lane = t & 31;
    int warp = t >> 5;
    if (lane == 0) ws[warp] = s;
    __syncthreads();
    if (warp == 0) {
        double v = ws[lane];
        #pragma unroll
        for (int o = 16; o > 0; o >>= 1)
            v += __shfl_down_sync(0xFFFFFFFFu, v, o);
        if (lane == 0) out[0] = (float)(v / TOTAL_ELEMS);
    }
}

// ---------------------------------------------------------------------------
extern "C" void kernel_launch(void* const* d_in, const int* in_sizes, int n_in,
                              void* d_out, int out_size) {
    const float* y_true = (const float*)d_in[0];
    const float* y_pred = (const float*)d_in[1];
    float* out = (float*)d_out;

    zero_scratch<<<256, 256>>>();
    pass1_gray_hist<<<1024, 256>>>(y_pred);
    select1<<<NB, 256>>>();
    pass2_compact<<<1024, 256>>>();
    select2<<<NB, 256>>>();
    pass3_loss<<<1024, 256>>>(y_true, y_pred);
    finalize<<<1, 1024>>>(out);
}

// round 5
// speedup vs baseline: 3.9638x; 1.0704x over previous
#include <cuda_runtime.h>
#include <math.h>

// Problem constants
#define NB      16
#define HW      262144           // 512*512
#define KRANK   104856u          // int(512*512*0.4 - 1)
#define NBINS   16384            // value-space bins: bin = min(16383, int(gray*16384))
#define CAP     4096             // per-batch candidate capacity (expected ~24)
#define TOTAL_ELEMS (16.0*3.0*512.0*512.0)

// Device scratch (zero-initialized .bss; finalize re-zeroes hist/cnt each run)
__device__ float        g_gray[NB * HW];
__device__ unsigned int g_hist[NB * NBINS];       // 1 MB
__device__ unsigned int g_cnt[NB];
__device__ float        g_buf[NB * CAP];
__device__ unsigned int g_bin[NB];
__device__ unsigned int g_rank[NB];
__device__ float        g_partial[1024];

__device__ __forceinline__ unsigned int gray_bin(float g) {
    int v = (int)(g * 16384.0f);
    if (v > NBINS - 1) v = NBINS - 1;
    if (v < 0) v = 0;
    return (unsigned int)v;
}

// ---------------------------------------------------------------------------
// K1: gray = (c0+c1+c2)/3, store gray, value-space histogram.
// 1024 blocks (64/batch) x 256 thr; 16 px/thread in TWO 8-px rounds
// (keeps live regs ~45 -> higher occupancy than fully front-batched).
// ---------------------------------------------------------------------------
__global__ void pass1_gray_hist(const float* __restrict__ yp) {
    int b = blockIdx.x >> 6;
    int r = blockIdx.x & 63;
    int t = threadIdx.x;

    const float4* c0 = (const float4*)yp + (size_t)b * 3 * (HW/4) + 0 * (HW/4) + r * 1024;
    const float4* c1 = (const float4*)yp + (size_t)b * 3 * (HW/4) + 1 * (HW/4) + r * 1024;
    const float4* c2 = (const float4*)yp + (size_t)b * 3 * (HW/4) + 2 * (HW/4) + r * 1024;
    float4* gr = (float4*)g_gray + (size_t)b * (HW/4) + r * 1024;
    unsigned int* h = g_hist + (size_t)b * NBINS;

    #pragma unroll
    for (int half = 0; half < 2; half++) {
        int o0 = t + half * 512;
        int o1 = o0 + 256;

        float4 a0 = c0[o0], a1 = c0[o1];
        float4 x0 = c1[o0], x1 = c1[o1];
        float4 y0 = c2[o0], y1 = c2[o1];

        float4 g0, g1;
        g0.x=(a0.x+x0.x+y0.x)/3.0f; g0.y=(a0.y+x0.y+y0.y)/3.0f;
        g0.z=(a0.z+x0.z+y0.z)/3.0f; g0.w=(a0.w+x0.w+y0.w)/3.0f;
        g1.x=(a1.x+x1.x+y1.x)/3.0f; g1.y=(a1.y+x1.y+y1.y)/3.0f;
        g1.z=(a1.z+x1.z+y1.z)/3.0f; g1.w=(a1.w+x1.w+y1.w)/3.0f;

        gr[o0] = g0;
        gr[o1] = g1;

        atomicAdd(&h[gray_bin(g0.x)],1u); atomicAdd(&h[gray_bin(g0.y)],1u);
        atomicAdd(&h[gray_bin(g0.z)],1u); atomicAdd(&h[gray_bin(g0.w)],1u);
        atomicAdd(&h[gray_bin(g1.x)],1u); atomicAdd(&h[gray_bin(g1.y)],1u);
        atomicAdd(&h[gray_bin(g1.z)],1u); atomicAdd(&h[gray_bin(g1.w)],1u);
    }
}

// ---------------------------------------------------------------------------
// K2: find value-bin containing rank KRANK.  16 blocks x 256 thr.
// ---------------------------------------------------------------------------
__global__ void select1() {
    int b = blockIdx.x;
    const uint4* h4 = (const uint4*)(g_hist + (size_t)b * NBINS);  // 4096 uint4
    __shared__ unsigned int partial[64];
    __shared__ unsigned int fine[256];
    __shared__ int s_chunk;
    __shared__ unsigned int s_rem;

    int warp = threadIdx.x >> 5;
    int lane = threadIdx.x & 31;

    #pragma unroll
    for (int it = 0; it < 8; it++) {
        int c = warp + 8 * it;
        uint4 v1 = h4[c * 64 + lane];
        uint4 v2 = h4[c * 64 + 32 + lane];
        unsigned int s = v1.x+v1.y+v1.z+v1.w + v2.x+v2.y+v2.z+v2.w;
        #pragma unroll
        for (int o = 16; o > 0; o >>= 1) s += __shfl_down_sync(0xFFFFFFFFu, s, o);
        if (lane == 0) partial[c] = s;
    }
    __syncthreads();

    if (threadIdx.x == 0) {
        unsigned int k = KRANK, cum = 0;
        int cb = 63;
        for (int j = 0; j < 64; j++) {
            if (k < cum + partial[j]) { cb = j; break; }
            cum += partial[j];
        }
        s_chunk = cb; s_rem = k - cum;
    }
    __syncthreads();

    int cb = s_chunk;
    fine[threadIdx.x] = g_hist[(size_t)b * NBINS + cb * 256 + threadIdx.x];
    __syncthreads();

    if (threadIdx.x == 0) {
        unsigned int k = s_rem, cum = 0;
        int fb = 255;
        for (int i = 0; i < 256; i++) {
            if (k < cum + fine[i]) { fb = i; break; }
            cum += fine[i];
        }
        g_bin[b]  = (unsigned int)(cb * 256 + fb);
        g_rank[b] = k - cum;        // rank within selected bin
    }
}

// ---------------------------------------------------------------------------
// K3: compact gray values in the selected bin (~24/batch).
// 2048 blocks (128/batch) x 256 thr; 8 px/thread (latency-bound pass,
// favor more resident warps).
// ---------------------------------------------------------------------------
__global__ void pass2_compact() {
    int b = blockIdx.x >> 7;
    int r = blockIdx.x & 127;
    int t = threadIdx.x;
    unsigned int bin = g_bin[b];

    const float4* gr = (const float4*)g_gray + (size_t)b * (HW/4) + r * 512;
    float4 g0 = gr[t], g1 = gr[t + 256];

    float v[8] = {g0.x,g0.y,g0.z,g0.w, g1.x,g1.y,g1.z,g1.w};

    #pragma unroll
    for (int i = 0; i < 8; i++) {
        if (gray_bin(v[i]) == bin) {
            unsigned int p = atomicAdd(&g_cnt[b], 1u);
            if (p < CAP) g_buf[(size_t)b * CAP + p] = v[i];
        }
    }
}

// ---------------------------------------------------------------------------
// K4: weighted L1 with INLINE exact threshold selection.
// 1024 blocks x 256 thr; 16 px/thread.
// Each block recomputes thr from the tiny candidate buffer (L2 broadcast).
// ---------------------------------------------------------------------------
__global__ void pass3_loss(const float* __restrict__ yt,
                           const float* __restrict__ yp) {
    int b = blockIdx.x >> 6;
    int r = blockIdx.x & 63;
    int t = threadIdx.x;

    // --- inline select2: exact rank-k among candidates of batch b ---
    __shared__ float s_thr;
    {
        unsigned int n = g_cnt[b];
        if (n > CAP) n = CAP;
        unsigned int k = g_rank[b];
        const float* buf = g_buf + (size_t)b * CAP;
        for (unsigned int i = t; i < n; i += 256) {
            float v = buf[i];
            unsigned int cl = 0, ce = 0;
            for (unsigned int j = 0; j < n; j++) {
                float w = buf[j];
                cl += (w < v);
                ce += (w == v);
            }
            if (cl <= k && k < cl + ce) s_thr = v;   // unique value
        }
    }
    __syncthreads();
    float thr = s_thr;

    size_t base4 = (size_t)b * 3 * (HW/4);
    const float4* p0 = (const float4*)yp + base4 + 0*(HW/4) + r*1024;
    const float4* p1 = (const float4*)yp + base4 + 1*(HW/4) + r*1024;
    const float4* p2 = (const float4*)yp + base4 + 2*(HW/4) + r*1024;
    const float4* q0 = (const float4*)yt + base4 + 0*(HW/4) + r*1024;
    const float4* q1 = (const float4*)yt + base4 + 1*(HW/4) + r*1024;
    const float4* q2 = (const float4*)yt + base4 + 2*(HW/4) + r*1024;

    float s = 0.0f;
    #pragma unroll
    for (int i = 0; i < 4; i++) {
        int o = t + i * 256;
        float4 a = p0[o], x = p1[o], y = p2[o];
        float4 u = q0[o], v = q1[o], w = q2[o];

        float gray, wt;
        gray = (a.x + x.x + y.x) / 3.0f;
        wt = (gray <= thr) ? 0.8f : 0.2f;
        s += wt * (fabsf(a.x-u.x) + fabsf(x.x-v.x) + fabsf(y.x-w.x));
        gray = (a.y + x.y + y.y) / 3.0f;
        wt = (gray <= thr) ? 0.8f : 0.2f;
        s += wt * (fabsf(a.y-u.y) + fabsf(x.y-v.y) + fabsf(y.y-w.y));
        gray = (a.z + x.z + y.z) / 3.0f;
        wt = (gray <= thr) ? 0.8f : 0.2f;
        s += wt * (fabsf(a.z-u.z) + fabsf(x.z-v.z) + fabsf(y.z-w.z));
        gray = (a.w + x.w + y.w) / 3.0f;
        wt = (gray <= thr) ? 0.8f : 0.2f;
        s += wt * (fabsf(a.w-u.w) + fabsf(x.w-v.w) + fabsf(y.w-w.w));
    }

    #pragma unroll
    for (int o = 16; o > 0; o >>= 1)
        s += __shfl_down_sync(0xFFFFFFFFu, s, o);

    __shared__ float ws[8];
    int lane = threadIdx.x & 31;
    int warp = threadIdx.x >> 5;
    if (lane == 0) ws[warp] = s;
    __syncthreads();
    if (warp == 0) {
        float vv = (lane < 8) ? ws[lane] : 0.0f;
        #pragma unroll
        for (int o = 4; o > 0; o >>= 1)
            vv += __shfl_down_sync(0xFFFFFFFFu, vv, o);
        if (lane == 0) g_partial[blockIdx.x] = vv;
    }
}

// ---------------------------------------------------------------------------
// K5: final reduction (block 0) + re-zero hist/counters for the next replay.
// 256 blocks x 256 thr.
// ---------------------------------------------------------------------------
__global__ void finalize(float* __restrict__ out) {
    int t = threadIdx.x;

    // zero the histogram slice for the next graph replay (65536 uint4 total)
    int zi = blockIdx.x * 256 + t;
    ((uint4*)g_hist)[zi] = make_uint4(0u, 0u, 0u, 0u);
    if (blockIdx.x == 1 && t < NB) g_cnt[t] = 0u;

    if (blockIdx.x != 0) return;

    double s = 0.0;
    #pragma unroll
    for (int i = 0; i < 4; i++)
        s += (double)g_partial[t + i * 256];

    #pragma unroll
    for (int o = 16; o > 0; o >>= 1)
        s += __shfl_down_sync(0xFFFFFFFFu, s, o);

    __shared__ double ws[8];
    int lane = t & 31;
    int warp = t >> 5;
    if (lane == 0) ws[warp] = s;
    __syncthreads();
    if (warp == 0) {
        double v = (lane < 8) ? ws[lane] : 0.0;
        #pragma unroll
        for (int o = 4; o > 0; o >>= 1)
            v += __shfl_down_sync(0xFFFFFFFFu, v, o);
        if (lane == 0) out[0] = (float)(v / TOTAL_ELEMS);
    }
}

// ---------------------------------------------------------------------------
extern "C" void kernel_launch(void* const* d_in, const int* in_sizes, int n_in,
                              void* d_out, int out_size) {
    const float* y_true = (const float*)d_in[0];
    const float* y_pred = (const float*)d_in[1];
    float* out = (float*)d_out;

    pass1_gray_hist<<<1024, 256>>>(y_pred);
    select1<<<NB, 256>>>();
    pass2_compact<<<2048, 256>>>();
    pass3_loss<<<1024, 256>>>(y_true, y_pred);
    finalize<<<256, 256>>>(out);
}